// round 13
// baseline (speedup 1.0000x reference)
#include <cuda_runtime.h>

// StrictOrthogonal via Cholesky-QR — fused persistent kernel v2.
// Grid 296 x 256, __launch_bounds__(256,2) -> 2 blocks/SM, all resident.
//   Phase A: G partials = X^H X slices       (all 296 blocks, <=56 rows each)
//   Phase B: slice reduce (blocks 259..295) -> Cholesky + W (block 0, 256 thr)
//   Phase C: Q = X W (blocks 1..256, 64-row tiles); X tile PRELOADED into
//            smem before spinning on W -> Cholesky latency hidden.
// Inter-block sync: threadfence + atomic counters; self-reset by last block.
// All fp sums fixed-order -> deterministic.

#define MROWS 16384
#define RCOLS 32
#define NBLK  296
#define NTHR  256
#define RPB   56               // rows per gram block (some tail blocks shorter)
#define NSLICE 37              // 37 * 8 = 296 partials
#define SMEM_BYTES 25088

__device__ float2 g_partials[NBLK][1024];
__device__ float2 g_p2[NSLICE][1024];
__device__ float2 g_W[1024];            // W = R^{-1} (upper, zeros below diag)
__device__ int g_cnt_a, g_cnt_b, g_flag_c, g_cnt_d;

__global__ void __launch_bounds__(NTHR, 2) fused_kernel(const float* __restrict__ x,
                                                        float* __restrict__ out) {
    __shared__ __align__(16) char smem_raw[SMEM_BYTES];
    const int t = threadIdx.x;
    const int b = blockIdx.x;

    // ===================== Phase A: partial Gram (all blocks) ==============
    {
        float*  s_re = reinterpret_cast<float*>(smem_raw);             // [56*32] 7168B
        float*  s_im = s_re + RPB * RCOLS;                             // 7168B
        float2 (*red)[256] = reinterpret_cast<float2(*)[256]>(s_im + RPB * RCOLS); // [4][256] 8KB

        const int start = b * RPB;
        const int nrows = max(0, min(RPB, MROWS - start));
        const float4* __restrict__ xr4 =
            reinterpret_cast<const float4*>(x) + (size_t)start * (RCOLS / 2);

        for (int n = t; n < nrows * (RCOLS / 2); n += NTHR) {
            float4 v = xr4[n];
            s_re[2 * n]     = v.x;  s_im[2 * n]     = v.y;
            s_re[2 * n + 1] = v.z;  s_im[2 * n + 1] = v.w;
        }
        __syncthreads();

        const int g  = t >> 6;          // K-group 0..3 (rows r == g mod 4)
        const int u  = t & 63;
        const int i0 = (u >> 3) * 4;    // 0,4,...,28
        const int j0 = (u & 7) * 4;     // 0,4,...,28

        float accx[4][4], accy[4][4];
        #pragma unroll
        for (int p = 0; p < 4; p++)
            #pragma unroll
            for (int q = 0; q < 4; q++) { accx[p][q] = 0.f; accy[p][q] = 0.f; }

        #pragma unroll 2
        for (int r = g; r < nrows; r += 4) {
            const float* rr = s_re + r * RCOLS;
            const float* ri = s_im + r * RCOLS;
            float4 arx = *reinterpret_cast<const float4*>(rr + i0);
            float4 ary = *reinterpret_cast<const float4*>(ri + i0);
            float4 brx = *reinterpret_cast<const float4*>(rr + j0);
            float4 bry = *reinterpret_cast<const float4*>(ri + j0);
            const float ax[4] = {arx.x, arx.y, arx.z, arx.w};
            const float ay[4] = {ary.x, ary.y, ary.z, ary.w};
            const float bx[4] = {brx.x, brx.y, brx.z, brx.w};
            const float by[4] = {bry.x, bry.y, bry.z, bry.w};
            #pragma unroll
            for (int p = 0; p < 4; p++)
                #pragma unroll
                for (int q = 0; q < 4; q++) {
                    // acc += conj(a_p) * b_q
                    accx[p][q] = fmaf(ax[p], bx[q], accx[p][q]);
                    accx[p][q] = fmaf(ay[p], by[q], accx[p][q]);
                    accy[p][q] = fmaf(ax[p], by[q], accy[p][q]);
                    accy[p][q] = fmaf(-ay[p], bx[q], accy[p][q]);
                }
        }
        __syncthreads();

        // cross-group reduce in 4 passes of 256 entries (rows [8p, 8p+8))
        #pragma unroll 1
        for (int p = 0; p < 4; p++) {
            if ((i0 >> 3) == p) {
                const int il = i0 & 7;                     // 0 or 4
                #pragma unroll
                for (int pp = 0; pp < 4; pp++)
                    #pragma unroll
                    for (int qq = 0; qq < 4; qq++)
                        red[g][(il + pp) * 32 + j0 + qq] =
                            make_float2(accx[pp][qq], accy[pp][qq]);
            }
            __syncthreads();
            {
                float2 s0 = red[0][t], s1 = red[1][t], s2 = red[2][t], s3 = red[3][t];
                g_partials[b][p * 256 + t] =
                    make_float2((s0.x + s1.x) + (s2.x + s3.x),
                                (s0.y + s1.y) + (s2.y + s3.y));
            }
            __syncthreads();
        }
    }

    // ===================== sync 1: partials ready ==========================
    __threadfence();
    __syncthreads();
    if (t == 0) atomicAdd(&g_cnt_a, 1);

    // ===================== Phase B1: slice reduce (blocks 259..295) ========
    if (b >= 259) {
        const int sb = b - 259;
        if (t == 0) { while (atomicAdd(&g_cnt_a, 0) < NBLK) { } }
        __syncthreads();
        const int b0 = sb * 8;
        #pragma unroll
        for (int l = 0; l < 2; l++) {
            const int e = t + 256 * l;              // float4 index 0..511
            float4 s = reinterpret_cast<const float4*>(g_partials[b0])[e];
            #pragma unroll
            for (int k = 1; k < 8; k++) {
                float4 p = reinterpret_cast<const float4*>(g_partials[b0 + k])[e];
                s.x += p.x; s.y += p.y; s.z += p.z; s.w += p.w;
            }
            reinterpret_cast<float4*>(g_p2[sb])[e] = s;
        }
        __threadfence();
        __syncthreads();
        if (t == 0) atomicAdd(&g_cnt_b, 1);
    }

    // ===================== Phase B2: Cholesky + W (block 0) ================
    if (b == 0) {
        if (t == 0) { while (atomicAdd(&g_cnt_b, 0) < NSLICE) { } }
        __syncthreads();

        float2 (*Gs)[RCOLS + 1] = reinterpret_cast<float2(*)[RCOLS + 1]>(smem_raw);          // 8448B
        float2 (*Rs)[RCOLS]     = reinterpret_cast<float2(*)[RCOLS]>(smem_raw + 8448);       // 8192B
        float2 (*Bs)[RCOLS + 1] = reinterpret_cast<float2(*)[RCOLS + 1]>(smem_raw + 16640);  // 8448B

        const int i  = t >> 3;          // row 0..31
        const int jb = 4 * (t & 7);     // columns jb..jb+3

        // final reduce of 37 slices: thread owns entries (i, jb..jb+3)
        {
            float4 s0 = reinterpret_cast<const float4*>(g_p2[0])[2 * t];
            float4 s1 = reinterpret_cast<const float4*>(g_p2[0])[2 * t + 1];
            #pragma unroll 4
            for (int k = 1; k < NSLICE; k++) {
                float4 p0 = reinterpret_cast<const float4*>(g_p2[k])[2 * t];
                float4 p1 = reinterpret_cast<const float4*>(g_p2[k])[2 * t + 1];
                s0.x += p0.x; s0.y += p0.y; s0.z += p0.z; s0.w += p0.w;
                s1.x += p1.x; s1.y += p1.y; s1.z += p1.z; s1.w += p1.w;
            }
            Gs[i][jb]     = make_float2(s0.x, s0.y);
            Gs[i][jb + 1] = make_float2(s0.z, s0.w);
            Gs[i][jb + 2] = make_float2(s1.x, s1.y);
            Gs[i][jb + 3] = make_float2(s1.z, s1.w);
            #pragma unroll
            for (int m = 0; m < 4; m++)
                Bs[i][jb + m] = make_float2((i == jb + m) ? 1.f : 0.f, 0.f);
        }
        __syncthreads();

        // sqrt-free Cholesky (lower triangle), 1 barrier per step
        #pragma unroll 1
        for (int k = 0; k < RCOLS; k++) {
            const float invg = 1.f / Gs[k][k].x;
            if (i > k) {
                float2 a = Gs[i][k];
                #pragma unroll
                for (int m = 0; m < 4; m++) {
                    const int jj = jb + m;
                    if (jj > k && jj <= i) {
                        float2 c = Gs[jj][k];
                        Gs[i][jj].x -= (a.x * c.x + a.y * c.y) * invg;
                        Gs[i][jj].y -= (a.y * c.x - a.x * c.y) * invg;
                    }
                }
            }
            __syncthreads();
        }

        // build R (upper): R[i][j] = conj(Gs[j][i]) * rsqrt(D_i), R[i][i]=sqrt(D_i)
        {
            const float s = rsqrtf(Gs[i][i].x);
            #pragma unroll
            for (int m = 0; m < 4; m++) {
                const int jj = jb + m;
                float2 rv = make_float2(0.f, 0.f);
                if (jj > i)       { float2 l = Gs[jj][i]; rv = make_float2(l.x * s, -l.y * s); }
                else if (jj == i) { rv = make_float2(sqrtf(Gs[i][i].x), 0.f); }
                Rs[i][jj] = rv;
            }
        }
        __syncthreads();

        // back-substitution: R W = I, 1 barrier per step
        #pragma unroll 1
        for (int k = RCOLS - 1; k >= 0; k--) {
            const float inv = 1.f / Rs[k][k].x;
            float2 r = Rs[i][k];
            #pragma unroll
            for (int m = 0; m < 4; m++) {
                const int jj = jb + m;
                float2 bk = Bs[k][jj];
                float2 w  = make_float2(bk.x * inv, bk.y * inv);
                if (i == k)
                    g_W[k * RCOLS + jj] = (jj >= k) ? w : make_float2(0.f, 0.f);
                if (i < k) {
                    Bs[i][jj].x -= r.x * w.x - r.y * w.y;
                    Bs[i][jj].y -= r.x * w.y + r.y * w.x;
                }
            }
            __syncthreads();
        }

        __threadfence();
        __syncthreads();
        if (t == 0) atomicExch(&g_flag_c, 1);
    }

    // ===================== Phase C: apply (blocks 1..256) ==================
    if (b >= 1 && b <= 256) {
        float2 (*Ws)[RCOLS]     = reinterpret_cast<float2(*)[RCOLS]>(smem_raw);            // 8192B
        float2 (*Xs)[RCOLS + 1] = reinterpret_cast<float2(*)[RCOLS + 1]>(smem_raw + 8192); // 16896B

        // PRELOAD X tile while block 0 runs Cholesky (no dependency on W)
        const int rowbase = (b - 1) * 64;
        const float4* __restrict__ src =
            reinterpret_cast<const float4*>(x) + (size_t)rowbase * (RCOLS / 2);
        #pragma unroll
        for (int l = 0; l < 4; l++) {
            const int n = t + NTHR * l;          // 0..1023
            const int r = n >> 4, q = n & 15;
            float4 f = src[n];
            Xs[r][2 * q]     = make_float2(f.x, f.y);
            Xs[r][2 * q + 1] = make_float2(f.z, f.w);
        }

        // wait for W
        if (t == 0) { while (atomicAdd(&g_flag_c, 0) == 0) { } }
        __syncthreads();

        #pragma unroll
        for (int l = 0; l < 4; l++) {
            const int e = t + NTHR * l;
            Ws[e >> 5][e & 31] = g_W[e];
        }
        __syncthreads();

        const int r  = t & 31;          // rows r and r+32
        const int c  = t >> 5;          // column group 0..7
        const int j0 = 4 * c;

        float ax[2][4], ay[2][4];
        #pragma unroll
        for (int m = 0; m < 4; m++) {
            ax[0][m] = 0.f; ay[0][m] = 0.f;
            ax[1][m] = 0.f; ay[1][m] = 0.f;
        }

        #pragma unroll 1
        for (int ch = 0; ch <= c; ch++) {          // triangular: ii < 4c+4
            #pragma unroll
            for (int k = 0; k < 4; k++) {
                const int ii = 4 * ch + k;
                const float2 a0 = Xs[r][ii];
                const float2 a1 = Xs[r + 32][ii];
                const float4 w01 = *reinterpret_cast<const float4*>(&Ws[ii][j0]);
                const float4 w23 = *reinterpret_cast<const float4*>(&Ws[ii][j0 + 2]);
                const float wx[4] = {w01.x, w01.z, w23.x, w23.z};
                const float wy[4] = {w01.y, w01.w, w23.y, w23.w};
                #pragma unroll
                for (int m = 0; m < 4; m++) {
                    ax[0][m] = fmaf(a0.x, wx[m], ax[0][m]); ax[0][m] = fmaf(-a0.y, wy[m], ax[0][m]);
                    ay[0][m] = fmaf(a0.x, wy[m], ay[0][m]); ay[0][m] = fmaf( a0.y, wx[m], ay[0][m]);
                    ax[1][m] = fmaf(a1.x, wx[m], ax[1][m]); ax[1][m] = fmaf(-a1.y, wy[m], ax[1][m]);
                    ay[1][m] = fmaf(a1.x, wy[m], ay[1][m]); ay[1][m] = fmaf( a1.y, wx[m], ay[1][m]);
                }
            }
        }

        float4* __restrict__ dst0 =
            reinterpret_cast<float4*>(out) + (size_t)(rowbase + r) * (RCOLS / 2) + 2 * c;
        float4* __restrict__ dst1 =
            reinterpret_cast<float4*>(out) + (size_t)(rowbase + r + 32) * (RCOLS / 2) + 2 * c;
        dst0[0] = make_float4(ax[0][0], ay[0][0], ax[0][1], ay[0][1]);
        dst0[1] = make_float4(ax[0][2], ay[0][2], ax[0][3], ay[0][3]);
        dst1[0] = make_float4(ax[1][0], ay[1][0], ax[1][1], ay[1][1]);
        dst1[1] = make_float4(ax[1][2], ay[1][2], ax[1][3], ay[1][3]);
    }

    // ===================== self-reset (last block) =========================
    if (t == 0) {
        int old = atomicAdd(&g_cnt_d, 1);
        if (old == NBLK - 1) {
            atomicExch(&g_cnt_a, 0);
            atomicExch(&g_cnt_b, 0);
            atomicExch(&g_flag_c, 0);
            atomicExch(&g_cnt_d, 0);
        }
    }
}

// ---------------------------------------------------------------------------
extern "C" void kernel_launch(void* const* d_in, const int* in_sizes, int n_in,
                              void* d_out, int out_size) {
    const float* x = (const float*)d_in[0];
    float* out = (float*)d_out;
    fused_kernel<<<NBLK, NTHR>>>(x, out);
}

// round 14
// speedup vs baseline: 1.0564x; 1.0564x over previous
#include <cuda_runtime.h>

// StrictOrthogonal via Cholesky-QR (all fp32), 3-kernel pipeline:
//   gram:    G partials = X^H X  (1024 blocks x 128 thr, 16 rows each)
//   redchol: slice reduce (32 blocks) -> Cholesky + W = R^{-1} (1 block, spin)
//   apply:   Q = X W  (1024 blocks x 128 thr, triangular register tiles)
// All fp sums fixed order -> deterministic.

#define MROWS 16384
#define RCOLS 32
#define GB 1024                // gram split-K blocks
#define RPB 16                 // rows per gram block (1024*16 = 16384)
#define NSLICE 32              // 32 * 32 = 1024 partials

__device__ float2 g_partials[GB][1024];
__device__ float2 g_p2[NSLICE][1024];
__device__ float2 g_W[1024];            // W = R^{-1} (upper, zeros below diag)
__device__ int    g_sync;               // reduce->chol flag (reset by gram b0)

// ---------------------------------------------------------------------------
// Kernel 1: partial Gram over 16 rows.  128 threads = 2 K-groups x 64; each
// thread owns a 4x4 complex tile of the 32x32 output, 8 row-iterations.
// Cross-group combine: group 0 writes smem, group 1 adds, then store.
// Low footprint (12.3KB smem, ~70 regs) -> ~6 blocks/SM -> 24 warps/SM.
// ---------------------------------------------------------------------------
__global__ void __launch_bounds__(128) gram_kernel(const float* __restrict__ x) {
    __shared__ float  s_re[RPB * RCOLS];          // 2KB
    __shared__ float  s_im[RPB * RCOLS];          // 2KB
    __shared__ float2 red[RCOLS * 33];            // padded rows, 8.25KB

    const int t = threadIdx.x;
    const int b = blockIdx.x;
    if (b == 0 && t == 0) g_sync = 0;             // stream-ordered reset for K2

    const float4* __restrict__ xr4 =
        reinterpret_cast<const float4*>(x) + (size_t)b * RPB * (RCOLS / 2);

    // 256 float4 loads, 2 per thread, coalesced; split into re/im planes
    #pragma unroll
    for (int l = 0; l < 2; l++) {
        const int n = t + 128 * l;
        float4 v = xr4[n];
        s_re[2 * n]     = v.x;  s_im[2 * n]     = v.y;
        s_re[2 * n + 1] = v.z;  s_im[2 * n + 1] = v.w;
    }
    __syncthreads();

    const int g  = t >> 6;          // K-group 0..1 (rows r == g mod 2)
    const int u  = t & 63;
    const int i0 = (u >> 3) * 4;    // 0,4,...,28
    const int j0 = (u & 7) * 4;     // 0,4,...,28

    float accx[4][4], accy[4][4];
    #pragma unroll
    for (int p = 0; p < 4; p++)
        #pragma unroll
        for (int q = 0; q < 4; q++) { accx[p][q] = 0.f; accy[p][q] = 0.f; }

    #pragma unroll 2
    for (int it = 0; it < RPB / 2; it++) {
        const int r = g + 2 * it;
        const float* rr = s_re + r * RCOLS;
        const float* ri = s_im + r * RCOLS;
        float4 arx = *reinterpret_cast<const float4*>(rr + i0);
        float4 ary = *reinterpret_cast<const float4*>(ri + i0);
        float4 brx = *reinterpret_cast<const float4*>(rr + j0);
        float4 bry = *reinterpret_cast<const float4*>(ri + j0);
        const float ax[4] = {arx.x, arx.y, arx.z, arx.w};
        const float ay[4] = {ary.x, ary.y, ary.z, ary.w};
        const float bx[4] = {brx.x, brx.y, brx.z, brx.w};
        const float by[4] = {bry.x, bry.y, bry.z, bry.w};
        #pragma unroll
        for (int p = 0; p < 4; p++)
            #pragma unroll
            for (int q = 0; q < 4; q++) {
                // acc += conj(a_p) * b_q
                accx[p][q] = fmaf(ax[p], bx[q], accx[p][q]);
                accx[p][q] = fmaf(ay[p], by[q], accx[p][q]);
                accy[p][q] = fmaf(ax[p], by[q], accy[p][q]);
                accy[p][q] = fmaf(-ay[p], bx[q], accy[p][q]);
            }
    }
    __syncthreads();   // plane reads done

    // group 0 writes its tile, group 1 accumulates into it
    if (g == 0) {
        #pragma unroll
        for (int p = 0; p < 4; p++)
            #pragma unroll
            for (int q = 0; q < 4; q++)
                red[(i0 + p) * 33 + j0 + q] = make_float2(accx[p][q], accy[p][q]);
    }
    __syncthreads();
    if (g == 1) {
        #pragma unroll
        for (int p = 0; p < 4; p++)
            #pragma unroll
            for (int q = 0; q < 4; q++) {
                float2 v = red[(i0 + p) * 33 + j0 + q];
                v.x += accx[p][q];
                v.y += accy[p][q];
                red[(i0 + p) * 33 + j0 + q] = v;
            }
    }
    __syncthreads();

    // store 1024 entries, 8 per thread, coalesced
    #pragma unroll
    for (int l = 0; l < 8; l++) {
        const int e = t + 128 * l;
        g_partials[b][e] = red[(e >> 5) * 33 + (e & 31)];
    }
}

// ---------------------------------------------------------------------------
// Kernel 2: blocks 0..31 reduce 32 partials each (fixed order) into g_p2;
// block 32 spins on g_sync, sums the 32 slices, runs Cholesky + W = R^{-1}.
// 33 blocks of 1024 threads, all resident in wave 1 -> spin safe.
// ---------------------------------------------------------------------------
__global__ void __launch_bounds__(1024) redchol_kernel() {
    const int t = threadIdx.x;

    if (blockIdx.x < NSLICE) {
        const int b0 = blockIdx.x * (GB / NSLICE);
        float sx0 = 0.f, sy0 = 0.f, sx1 = 0.f, sy1 = 0.f;
        #pragma unroll 4
        for (int k = 0; k < GB / NSLICE; k += 2) {
            float2 p0 = g_partials[b0 + k][t];
            float2 p1 = g_partials[b0 + k + 1][t];
            sx0 += p0.x; sy0 += p0.y;
            sx1 += p1.x; sy1 += p1.y;
        }
        g_p2[blockIdx.x][t] = make_float2(sx0 + sx1, sy0 + sy1);
        __threadfence();
        __syncthreads();
        if (t == 0) atomicAdd(&g_sync, 1);
        return;
    }

    // --- chol block: wait for all slices ---
    if (t == 0) {
        while (atomicAdd(&g_sync, 0) < NSLICE) { }
        __threadfence();
    }
    __syncthreads();

    __shared__ float2 Gs[RCOLS][RCOLS + 1];
    __shared__ float2 Rs[RCOLS][RCOLS];
    __shared__ float2 Bs[RCOLS][RCOLS + 1];
    const int i = t >> 5, j = t & 31;

    {
        float sx = 0.f, sy = 0.f;
        #pragma unroll
        for (int s = 0; s < NSLICE; s++) {
            float2 p = g_p2[s][t];
            sx += p.x; sy += p.y;
        }
        Gs[i][j] = make_float2(sx, sy);
        Bs[i][j] = make_float2((i == j) ? 1.f : 0.f, 0.f);
    }
    __syncthreads();

    // --- sqrt-free Cholesky (lower triangle), 1 barrier per step ---
    #pragma unroll 1
    for (int k = 0; k < RCOLS; k++) {
        const float invg = 1.f / Gs[k][k].x;
        if (i > k && j > k && j <= i) {
            float2 a = Gs[i][k], c = Gs[j][k];
            float pr = a.x * c.x + a.y * c.y;    // (a * conj(c)).re
            float pi = a.y * c.x - a.x * c.y;    // (a * conj(c)).im
            Gs[i][j].x -= pr * invg;
            Gs[i][j].y -= pi * invg;
        }
        __syncthreads();
    }

    // --- build R (upper): R[i][j] = conj(Gs[j][i]) * rsqrt(D_i), R[i][i]=sqrt(D_i)
    float2 rv = make_float2(0.f, 0.f);
    if (j > i) {
        float2 l = Gs[j][i];
        float  s = rsqrtf(Gs[i][i].x);
        rv = make_float2(l.x * s, -l.y * s);
    } else if (j == i) {
        rv = make_float2(sqrtf(Gs[i][i].x), 0.f);
    }
    Rs[i][j] = rv;
    __syncthreads();

    // --- back-substitution: R W = I (W upper incl. diag), 1 barrier/step ---
    #pragma unroll 1
    for (int k = RCOLS - 1; k >= 0; k--) {
        const float inv = 1.f / Rs[k][k].x;
        float2 bk = Bs[k][j];
        float2 w  = make_float2(bk.x * inv, bk.y * inv);
        if (i == k)
            g_W[k * RCOLS + j] = (j >= k) ? w : make_float2(0.f, 0.f);
        if (i < k) {
            float2 r = Rs[i][k];
            Bs[i][j].x -= r.x * w.x - r.y * w.y;
            Bs[i][j].y -= r.x * w.y + r.y * w.x;
        }
        __syncthreads();
    }
}

// ---------------------------------------------------------------------------
// Kernel 3: Q = X * W.  16-row tiles, 128 threads = 16 rows x 8 col-groups;
// thread does 1 row x 4 cols, triangular chunks ch <= c (c = t>>4 so the
// chunk count is warp-uniform).  Grid 1024 -> ~27 warps/SM.
// ---------------------------------------------------------------------------
#define AROWS 16
__global__ void __launch_bounds__(128) apply_kernel(const float* __restrict__ x,
                                                    float* __restrict__ out) {
    __shared__ __align__(16) float2 Ws[RCOLS][RCOLS];   // 8KB
    __shared__ float2 Xs[AROWS][RCOLS + 1];             // 4.2KB, padded rows
    const int t = threadIdx.x;

    // W: 512 float4 = 4 per thread
    #pragma unroll
    for (int l = 0; l < 4; l++) {
        const int n = t + 128 * l;
        reinterpret_cast<float4*>(&Ws[0][0])[n] =
            reinterpret_cast<const float4*>(g_W)[n];
    }

    const int rowbase = blockIdx.x * AROWS;
    const float4* __restrict__ src =
        reinterpret_cast<const float4*>(x) + (size_t)rowbase * (RCOLS / 2);
    // 16 rows x 16 float4 = 256 float4, 2 per thread, coalesced
    #pragma unroll
    for (int l = 0; l < 2; l++) {
        const int n = t + 128 * l;
        const int r = n >> 4, q = n & 15;
        float4 f = src[n];
        Xs[r][2 * q]     = make_float2(f.x, f.y);
        Xs[r][2 * q + 1] = make_float2(f.z, f.w);
    }
    __syncthreads();

    const int r  = t & 15;          // row within tile
    const int c  = t >> 4;          // column group 0..7 (warp-uniform-ish)
    const int j0 = 4 * c;

    float ax[4], ay[4];
    #pragma unroll
    for (int m = 0; m < 4; m++) { ax[m] = 0.f; ay[m] = 0.f; }

    #pragma unroll 1
    for (int ch = 0; ch <= c; ch++) {          // triangular: ii < 4c+4
        #pragma unroll
        for (int k = 0; k < 4; k++) {
            const int ii = 4 * ch + k;
            const float2 a = Xs[r][ii];
            const float4 w01 = *reinterpret_cast<const float4*>(&Ws[ii][j0]);
            const float4 w23 = *reinterpret_cast<const float4*>(&Ws[ii][j0 + 2]);
            const float wx[4] = {w01.x, w01.z, w23.x, w23.z};
            const float wy[4] = {w01.y, w01.w, w23.y, w23.w};
            #pragma unroll
            for (int m = 0; m < 4; m++) {
                ax[m] = fmaf(a.x, wx[m], ax[m]); ax[m] = fmaf(-a.y, wy[m], ax[m]);
                ay[m] = fmaf(a.x, wy[m], ay[m]); ay[m] = fmaf( a.y, wx[m], ay[m]);
            }
        }
    }

    float4* __restrict__ dst =
        reinterpret_cast<float4*>(out) + (size_t)(rowbase + r) * (RCOLS / 2) + 2 * c;
    dst[0] = make_float4(ax[0], ay[0], ax[1], ay[1]);
    dst[1] = make_float4(ax[2], ay[2], ax[3], ay[3]);
}

// ---------------------------------------------------------------------------
extern "C" void kernel_launch(void* const* d_in, const int* in_sizes, int n_in,
                              void* d_out, int out_size) {
    const float* x = (const float*)d_in[0];
    float* out = (float*)d_out;
    gram_kernel<<<GB, 128>>>(x);
    redchol_kernel<<<NSLICE + 1, 1024>>>();
    apply_kernel<<<MROWS / AROWS, 128>>>(x, out);
}

// round 16
// speedup vs baseline: 1.1230x; 1.0630x over previous
#include <cuda_runtime.h>

// StrictOrthogonal via Cholesky-QR (fp32, packed f32x2 FMA on the hot paths):
//   gram:    G partials = X^H X  (512 blocks x 256 thr, 32 rows each)
//   redchol: slice reduce (32 blocks) -> Cholesky + W = R^{-1} (1 block, spin)
//   apply:   Q = X W  (1024 blocks x 128 thr, triangular, f32x2)
// Split-accumulator complex trick: acc1 += (ax,ax)*(bx,by); acc2 += (ay,ay)*(bx,by);
//   conj(a)*b: G = (acc1.x + acc2.y, acc1.y - acc2.x)
//   a*w      : q = (acc1.x - acc2.y, acc1.y + acc2.x)
// All fp sums fixed order -> deterministic.

#define MROWS 16384
#define RCOLS 32
#define GB 512                 // gram split-K blocks
#define RPB 32                 // rows per gram block (512*32 = 16384)
#define NSLICE 32              // 32 * 16 = 512 partials

typedef unsigned long long ull;

__device__ float2 g_partials[GB][1024];
__device__ float2 g_p2[NSLICE][1024];
__device__ float2 g_W[1024];            // W = R^{-1} (upper, zeros below diag)
__device__ int    g_sync;               // reduce->chol flag (reset by gram b0)

__device__ __forceinline__ ull pk2(float a, float b) {
    ull r; asm("mov.b64 %0,{%1,%2};" : "=l"(r) : "f"(a), "f"(b)); return r;
}
__device__ __forceinline__ void upk2(ull v, float& a, float& b) {
    asm("mov.b64 {%0,%1},%2;" : "=f"(a), "=f"(b) : "l"(v));
}
__device__ __forceinline__ void fma2(ull& d, ull a, ull b) {
    asm("fma.rn.f32x2 %0, %1, %2, %0;" : "+l"(d) : "l"(a), "l"(b));
}

// ---------------------------------------------------------------------------
// Kernel 1: partial Gram over 32 rows.  256 threads = 2 K-groups x 128; each
// thread owns a 4x2 complex tile (i0 = 4*(u>>4), j0 = 2*(u&15)), 16 row-iters.
// X tile is a VERBATIM float2 copy (b operands are pre-packed by layout).
// Inner row-iter: 3 vector LDS + 8 packs + 16 FMA2 (was 64 scalar FFMA).
// ---------------------------------------------------------------------------
__global__ void __launch_bounds__(256) gram_kernel(const float* __restrict__ x) {
    __shared__ __align__(16) float2 s_x[RPB][RCOLS];      // 8KB verbatim tile
    __shared__ float2 red[RCOLS][RCOLS + 1];              // 8.4KB

    const int t = threadIdx.x;
    const int b = blockIdx.x;
    if (b == 0 && t == 0) g_sync = 0;       // stream-ordered reset for K2

    // verbatim 8KB copy: 512 float4, 2 per thread, coalesced
    {
        const float4* __restrict__ xr4 =
            reinterpret_cast<const float4*>(x) + (size_t)b * RPB * (RCOLS / 2);
        float4* sx4 = reinterpret_cast<float4*>(&s_x[0][0]);
        sx4[t]       = xr4[t];
        sx4[t + 256] = xr4[t + 256];
    }
    __syncthreads();

    const int g  = t >> 7;           // K-group 0..1 (rows r == g mod 2)
    const int u  = t & 127;
    const int i0 = (u >> 4) * 4;     // 0,4,...,28
    const int j0 = (u & 15) * 2;     // 0,2,...,30

    ull acc1[4][2], acc2[4][2];
    #pragma unroll
    for (int p = 0; p < 4; p++)
        #pragma unroll
        for (int q = 0; q < 2; q++) { acc1[p][q] = 0ull; acc2[p][q] = 0ull; }

    #pragma unroll 4
    for (int it = 0; it < RPB / 2; it++) {
        const int r = g + 2 * it;
        float4 a01 = *reinterpret_cast<const float4*>(&s_x[r][i0]);
        float4 a23 = *reinterpret_cast<const float4*>(&s_x[r][i0 + 2]);
        ulonglong2 bb = *reinterpret_cast<const ulonglong2*>(&s_x[r][j0]);
        const ull axx[4] = {pk2(a01.x, a01.x), pk2(a01.z, a01.z),
                            pk2(a23.x, a23.x), pk2(a23.z, a23.z)};
        const ull ayy[4] = {pk2(a01.y, a01.y), pk2(a01.w, a01.w),
                            pk2(a23.y, a23.y), pk2(a23.w, a23.w)};
        #pragma unroll
        for (int p = 0; p < 4; p++) {
            fma2(acc1[p][0], axx[p], bb.x);
            fma2(acc1[p][1], axx[p], bb.y);
            fma2(acc2[p][0], ayy[p], bb.x);
            fma2(acc2[p][1], ayy[p], bb.y);
        }
    }

    // cross-group combine: group 0 writes, group 1 adds
    if (g == 0) {
        #pragma unroll
        for (int p = 0; p < 4; p++)
            #pragma unroll
            for (int q = 0; q < 2; q++) {
                float s1x, s1y, s2x, s2y;
                upk2(acc1[p][q], s1x, s1y);
                upk2(acc2[p][q], s2x, s2y);
                red[i0 + p][j0 + q] = make_float2(s1x + s2y, s1y - s2x);
            }
    }
    __syncthreads();
    if (g == 1) {
        #pragma unroll
        for (int p = 0; p < 4; p++)
            #pragma unroll
            for (int q = 0; q < 2; q++) {
                float s1x, s1y, s2x, s2y;
                upk2(acc1[p][q], s1x, s1y);
                upk2(acc2[p][q], s2x, s2y);
                float2 v = red[i0 + p][j0 + q];
                v.x += s1x + s2y;
                v.y += s1y - s2x;
                red[i0 + p][j0 + q] = v;
            }
    }
    __syncthreads();

    // store 1024 entries, 4 per thread, coalesced
    #pragma unroll
    for (int l = 0; l < 4; l++) {
        const int e = t + 256 * l;
        g_partials[b][e] = red[e >> 5][e & 31];
    }
}

// ---------------------------------------------------------------------------
// Kernel 2: blocks 0..31 reduce 16 partials each (fixed order) into g_p2;
// block 32 spins on g_sync, sums the 32 slices, runs Cholesky + W = R^{-1}.
// 33 blocks of 1024 threads, all resident in wave 1 -> spin safe.
// ---------------------------------------------------------------------------
__global__ void __launch_bounds__(1024) redchol_kernel() {
    const int t = threadIdx.x;

    if (blockIdx.x < NSLICE) {
        const int b0 = blockIdx.x * (GB / NSLICE);
        float sx0 = 0.f, sy0 = 0.f, sx1 = 0.f, sy1 = 0.f;
        #pragma unroll 4
        for (int k = 0; k < GB / NSLICE; k += 2) {
            float2 p0 = g_partials[b0 + k][t];
            float2 p1 = g_partials[b0 + k + 1][t];
            sx0 += p0.x; sy0 += p0.y;
            sx1 += p1.x; sy1 += p1.y;
        }
        g_p2[blockIdx.x][t] = make_float2(sx0 + sx1, sy0 + sy1);
        __threadfence();
        __syncthreads();
        if (t == 0) atomicAdd(&g_sync, 1);
        return;
    }

    // --- chol block: wait for all slices ---
    if (t == 0) {
        while (atomicAdd(&g_sync, 0) < NSLICE) { }
        __threadfence();
    }
    __syncthreads();

    __shared__ float2 Gs[RCOLS][RCOLS + 1];
    __shared__ float2 Rs[RCOLS][RCOLS];
    __shared__ float2 Bs[RCOLS][RCOLS + 1];
    const int i = t >> 5, j = t & 31;

    {
        float sx = 0.f, sy = 0.f;
        #pragma unroll
        for (int s = 0; s < NSLICE; s++) {
            float2 p = g_p2[s][t];
            sx += p.x; sy += p.y;
        }
        Gs[i][j] = make_float2(sx, sy);
        Bs[i][j] = make_float2((i == j) ? 1.f : 0.f, 0.f);
    }
    __syncthreads();

    // --- sqrt-free Cholesky (lower triangle), 1 barrier per step ---
    #pragma unroll 1
    for (int k = 0; k < RCOLS; k++) {
        const float invg = 1.f / Gs[k][k].x;
        if (i > k && j > k && j <= i) {
            float2 a = Gs[i][k], c = Gs[j][k];
            float pr = a.x * c.x + a.y * c.y;    // (a * conj(c)).re
            float pi = a.y * c.x - a.x * c.y;    // (a * conj(c)).im
            Gs[i][j].x -= pr * invg;
            Gs[i][j].y -= pi * invg;
        }
        __syncthreads();
    }

    // --- build R (upper): R[i][j] = conj(Gs[j][i]) * rsqrt(D_i), R[i][i]=sqrt(D_i)
    float2 rv = make_float2(0.f, 0.f);
    if (j > i) {
        float2 l = Gs[j][i];
        float  s = rsqrtf(Gs[i][i].x);
        rv = make_float2(l.x * s, -l.y * s);
    } else if (j == i) {
        rv = make_float2(sqrtf(Gs[i][i].x), 0.f);
    }
    Rs[i][j] = rv;
    __syncthreads();

    // --- back-substitution: R W = I (W upper incl. diag), 1 barrier/step ---
    #pragma unroll 1
    for (int k = RCOLS - 1; k >= 0; k--) {
        const float inv = 1.f / Rs[k][k].x;
        float2 bk = Bs[k][j];
        float2 w  = make_float2(bk.x * inv, bk.y * inv);
        if (i == k)
            g_W[k * RCOLS + j] = (j >= k) ? w : make_float2(0.f, 0.f);
        if (i < k) {
            float2 r = Rs[i][k];
            Bs[i][j].x -= r.x * w.x - r.y * w.y;
            Bs[i][j].y -= r.x * w.y + r.y * w.x;
        }
        __syncthreads();
    }
}

// ---------------------------------------------------------------------------
// Kernel 3: Q = X * W, f32x2.  16-row tiles, 128 threads = 16 rows x 8
// col-groups of 4; triangular chunks ch <= c.  Per ii: 1 LDS.64 (a) + 2
// 16B LDS (w row) + 2 packs + 8 FMA2 (was 16 FFMA).
// ---------------------------------------------------------------------------
#define AROWS 16
__global__ void __launch_bounds__(128) apply_kernel(const float* __restrict__ x,
                                                    float* __restrict__ out) {
    __shared__ __align__(16) float2 Ws[RCOLS][RCOLS];   // 8KB
    __shared__ __align__(16) float2 Xs[AROWS][RCOLS + 1];
    const int t = threadIdx.x;

    // W: 512 float4 = 4 per thread
    #pragma unroll
    for (int l = 0; l < 4; l++) {
        const int n = t + 128 * l;
        reinterpret_cast<float4*>(&Ws[0][0])[n] =
            reinterpret_cast<const float4*>(g_W)[n];
    }

    const int rowbase = blockIdx.x * AROWS;
    const float4* __restrict__ src =
        reinterpret_cast<const float4*>(x) + (size_t)rowbase * (RCOLS / 2);
    #pragma unroll
    for (int l = 0; l < 2; l++) {
        const int n = t + 128 * l;
        const int r = n >> 4, q = n & 15;
        float4 f = src[n];
        Xs[r][2 * q]     = make_float2(f.x, f.y);
        Xs[r][2 * q + 1] = make_float2(f.z, f.w);
    }
    __syncthreads();

    const int r  = t & 15;          // row within tile
    const int c  = t >> 4;          // column group 0..7
    const int j0 = 4 * c;

    ull acc1[4], acc2[4];
    #pragma unroll
    for (int m = 0; m < 4; m++) { acc1[m] = 0ull; acc2[m] = 0ull; }

    #pragma unroll 1
    for (int ch = 0; ch <= c; ch++) {          // triangular: ii < 4c+4
        #pragma unroll
        for (int k = 0; k < 4; k++) {
            const int ii = 4 * ch + k;
            const float2 a = Xs[r][ii];
            const ull axx = pk2(a.x, a.x);
            const ull ayy = pk2(a.y, a.y);
            ulonglong2 w01 = *reinterpret_cast<const ulonglong2*>(&Ws[ii][j0]);
            ulonglong2 w23 = *reinterpret_cast<const ulonglong2*>(&Ws[ii][j0 + 2]);
            fma2(acc1[0], axx, w01.x); fma2(acc2[0], ayy, w01.x);
            fma2(acc1[1], axx, w01.y); fma2(acc2[1], ayy, w01.y);
            fma2(acc1[2], axx, w23.x); fma2(acc2[2], ayy, w23.x);
            fma2(acc1[3], axx, w23.y); fma2(acc2[3], ayy, w23.y);
        }
    }

    float qx[4], qy[4];
    #pragma unroll
    for (int m = 0; m < 4; m++) {
        float s1x, s1y, s2x, s2y;
        upk2(acc1[m], s1x, s1y);
        upk2(acc2[m], s2x, s2y);
        qx[m] = s1x - s2y;          // a*w (no conj)
        qy[m] = s1y + s2x;
    }

    float4* __restrict__ dst =
        reinterpret_cast<float4*>(out) + (size_t)(rowbase + r) * (RCOLS / 2) + 2 * c;
    dst[0] = make_float4(qx[0], qy[0], qx[1], qy[1]);
    dst[1] = make_float4(qx[2], qy[2], qx[3], qy[3]);
}

// ---------------------------------------------------------------------------
extern "C" void kernel_launch(void* const* d_in, const int* in_sizes, int n_in,
                              void* d_out, int out_size) {
    const float* x = (const float*)d_in[0];
    float* out = (float*)d_out;
    gram_kernel<<<GB, 256>>>(x);
    redchol_kernel<<<NSLICE + 1, 1024>>>();
    apply_kernel<<<MROWS / AROWS, 128>>>(x, out);
}